// round 3
// baseline (speedup 1.0000x reference)
#include <cuda_runtime.h>
#include <math.h>

#define NT 8192
#define CD 128
#define NCLUS 256
#define SQRT_C 11.313708498984761f
#define FLTMAX 3.402823466e38f

// ---------------- scratch (static device globals; no allocs) ----------------
__device__ float g_D2[(long long)NT * NT];   // 256 MB squared-distance matrix (unclamped)
__device__ float g_sq[NT];
__device__ float g_density[NT];
__device__ float g_score[NT];
__device__ unsigned int g_maxbits;

// ---------------- jax threefry2x32 noise, bit-exact ----------------
__device__ __forceinline__ unsigned int rotl(unsigned int x, int d) {
    return (x << d) | (x >> (32 - d));
}

__device__ float jax_noise(int i) {
    unsigned int x0, x1;
    if (i < 4096) { x0 = (unsigned int)i;          x1 = (unsigned int)(i + 4096); }
    else          { x0 = (unsigned int)(i - 4096); x1 = (unsigned int)i; }
    const unsigned int ks0 = 0u, ks1 = 1u, ks2 = 0u ^ 1u ^ 0x1BD11BDAu;
    x0 += ks0; x1 += ks1;
#define TFR(r) { x0 += x1; x1 = rotl(x1, r); x1 ^= x0; }
    TFR(13) TFR(15) TFR(26) TFR(6)
    x0 += ks1; x1 += ks2 + 1u;
    TFR(17) TFR(29) TFR(16) TFR(24)
    x0 += ks2; x1 += ks0 + 2u;
    TFR(13) TFR(15) TFR(26) TFR(6)
    x0 += ks0; x1 += ks1 + 3u;
    TFR(17) TFR(29) TFR(16) TFR(24)
    x0 += ks1; x1 += ks2 + 4u;
    TFR(13) TFR(15) TFR(26) TFR(6)
    x0 += ks2; x1 += ks0 + 5u;
#undef TFR
    unsigned int bits = (i < 4096) ? x0 : x1;
    unsigned int fb = (bits >> 9) | 0x3f800000u;
    return __uint_as_float(fb) - 1.0f;   // uniform [0,1), exactly jax's mapping
}

// ---------------- kernel 1: row sum-of-squares + reset global max ----------------
__global__ void k_rownorm(const float* __restrict__ X) {
    if (blockIdx.x == 0 && threadIdx.x == 0) g_maxbits = 0u;
    int row = blockIdx.x * 8 + (threadIdx.x >> 5);
    int lane = threadIdx.x & 31;
    const float4 v = reinterpret_cast<const float4*>(X)[(long long)row * 32 + lane];
    float s = __fmul_rn(v.x, v.x);
    s = __fadd_rn(s, __fmul_rn(v.y, v.y));
    s = __fadd_rn(s, __fmul_rn(v.z, v.z));
    s = __fadd_rn(s, __fmul_rn(v.w, v.w));
    #pragma unroll
    for (int off = 16; off > 0; off >>= 1)
        s = __fadd_rn(s, __shfl_xor_sync(0xFFFFFFFFu, s, off));
    if (lane == 0) g_sq[row] = s;
}

// ---------------- kernel 2: symmetric SGEMM -> D2 (plain FFMA) ----------------
// Upper-triangle tile pairs (bi<=bj), 128x128 tile per block, 256 threads, 8x8/thread.
__global__ void __launch_bounds__(256) k_gemm(const float* __restrict__ X) {
    __shared__ float As[8][128];
    __shared__ float Bs[8][128];

    // linear block id -> (bi, bj) with bi <= bj over 64x64 tiles
    int rem = blockIdx.x;
    int bi = 0, span = 64;
    while (rem >= span) { rem -= span; span--; bi++; }
    int bj = bi + rem;

    const int rows = bi * 128, cols = bj * 128;
    const int tid = threadIdx.x;
    const int tx = tid & 15, ty = tid >> 4;

    float acc[8][8];
    #pragma unroll
    for (int m = 0; m < 8; m++)
        #pragma unroll
        for (int n = 0; n < 8; n++) acc[m][n] = 0.0f;

    const int lrow = tid >> 1;            // 0..127
    const int lk = (tid & 1) * 4;         // 0 or 4

    for (int k0 = 0; k0 < CD; k0 += 8) {
        float4 va = *reinterpret_cast<const float4*>(X + (long long)(rows + lrow) * CD + k0 + lk);
        float4 vb = *reinterpret_cast<const float4*>(X + (long long)(cols + lrow) * CD + k0 + lk);
        __syncthreads();
        As[lk + 0][lrow] = va.x; As[lk + 1][lrow] = va.y;
        As[lk + 2][lrow] = va.z; As[lk + 3][lrow] = va.w;
        Bs[lk + 0][lrow] = vb.x; Bs[lk + 1][lrow] = vb.y;
        Bs[lk + 2][lrow] = vb.z; Bs[lk + 3][lrow] = vb.w;
        __syncthreads();

        #pragma unroll
        for (int kk = 0; kk < 8; kk++) {
            float4 a0 = *reinterpret_cast<float4*>(&As[kk][ty * 8]);
            float4 a1 = *reinterpret_cast<float4*>(&As[kk][ty * 8 + 4]);
            float4 b0 = *reinterpret_cast<float4*>(&Bs[kk][tx * 8]);
            float4 b1 = *reinterpret_cast<float4*>(&Bs[kk][tx * 8 + 4]);
            float am[8] = {a0.x, a0.y, a0.z, a0.w, a1.x, a1.y, a1.z, a1.w};
            float bn[8] = {b0.x, b0.y, b0.z, b0.w, b1.x, b1.y, b1.z, b1.w};
            #pragma unroll
            for (int m = 0; m < 8; m++)
                #pragma unroll
                for (int n = 0; n < 8; n++)
                    acc[m][n] = __fmaf_rn(am[m], bn[n], acc[m][n]);
        }
    }

    // epilogue: d2 = (sq_i + sq_j) - 2*dot   (matches jax op order)
    float sr[8], sc[8];
    #pragma unroll
    for (int m = 0; m < 8; m++) sr[m] = g_sq[rows + ty * 8 + m];
    #pragma unroll
    for (int n = 0; n < 8; n++) sc[n] = g_sq[cols + tx * 8 + n];

    float v[8][8];
    #pragma unroll
    for (int m = 0; m < 8; m++)
        #pragma unroll
        for (int n = 0; n < 8; n++)
            v[m][n] = __fadd_rn(__fadd_rn(sr[m], sc[n]), -2.0f * acc[m][n]);

    #pragma unroll
    for (int m = 0; m < 8; m++) {
        long long base = (long long)(rows + ty * 8 + m) * NT + cols + tx * 8;
        *reinterpret_cast<float4*>(g_D2 + base)     = make_float4(v[m][0], v[m][1], v[m][2], v[m][3]);
        *reinterpret_cast<float4*>(g_D2 + base + 4) = make_float4(v[m][4], v[m][5], v[m][6], v[m][7]);
    }
    if (bi != bj) {
        #pragma unroll
        for (int n = 0; n < 8; n++) {
            long long base = (long long)(cols + tx * 8 + n) * NT + rows + ty * 8;
            *reinterpret_cast<float4*>(g_D2 + base)     = make_float4(v[0][n], v[1][n], v[2][n], v[3][n]);
            *reinterpret_cast<float4*>(g_D2 + base + 4) = make_float4(v[4][n], v[5][n], v[6][n], v[7][n]);
        }
    }
}

// ---------------- kernel 3 (pass A): 5-NN density + global max d2 ----------------
__global__ void __launch_bounds__(256) k_knn() {
    const int i = blockIdx.x;
    const int t = threadIdx.x;
    const float* __restrict__ row = g_D2 + (long long)i * NT;

    float s0 = FLTMAX, s1 = FLTMAX, s2 = FLTMAX, s3 = FLTMAX, s4 = FLTMAX;
    float vmax = -FLTMAX;

    for (int j = t; j < NT; j += 256) {
        float x = row[j];
        vmax = fmaxf(vmax, x);
        if (x < s4) {
            if (x < s3) {
                s4 = s3;
                if (x < s2) {
                    s3 = s2;
                    if (x < s1) {
                        s2 = s1;
                        if (x < s0) { s1 = s0; s0 = x; } else s1 = x;
                    } else s2 = x;
                } else s3 = x;
            } else s4 = x;
        }
    }

    __shared__ float sh[256 * 5];
    __shared__ float shm[256];
    sh[t * 5 + 0] = s0; sh[t * 5 + 1] = s1; sh[t * 5 + 2] = s2;
    sh[t * 5 + 3] = s3; sh[t * 5 + 4] = s4;
    shm[t] = vmax;
    __syncthreads();

    for (int stride = 128; stride >= 1; stride >>= 1) {
        if (t < stride) {
            float* A = &sh[t * 5];
            float* B = &sh[(t + stride) * 5];
            float o[5];
            int ia = 0, ib = 0;
            #pragma unroll
            for (int q = 0; q < 5; q++) {
                float av = (ia < 5) ? A[ia] : FLTMAX;
                float bv = (ib < 5) ? B[ib] : FLTMAX;
                if (av <= bv) { o[q] = av; ia++; } else { o[q] = bv; ib++; }
            }
            #pragma unroll
            for (int q = 0; q < 5; q++) A[q] = o[q];
            shm[t] = fmaxf(shm[t], shm[t + stride]);
        }
        __syncthreads();
    }

    if (t == 0) {
        atomicMax(&g_maxbits, __float_as_uint(fmaxf(shm[0], 0.0f)));
        float accv = 0.0f;
        #pragma unroll
        for (int q = 0; q < 5; q++) {
            float d = __fdiv_rn(__fsqrt_rn(fmaxf(sh[q], 0.0f)), SQRT_C);
            accv = __fadd_rn(accv, __fmul_rn(d, d));
        }
        float mean = __fdiv_rn(accv, 5.0f);
        float dens = (float)exp(-(double)mean);
        dens = __fadd_rn(dens, __fmul_rn(jax_noise(i), 1e-6f));
        g_density[i] = dens;
    }
}

// ---------------- kernel 4 (pass B): dist_parent + score ----------------
__global__ void __launch_bounds__(256) k_parent() {
    const int i = blockIdx.x;
    const int t = threadIdx.x;
    const float di = g_density[i];
    const float* __restrict__ row = g_D2 + (long long)i * NT;

    float lmin = FLTMAX;
    for (int j = t; j < NT; j += 256) {
        float dj = __ldg(&g_density[j]);
        if (dj > di) lmin = fminf(lmin, fmaxf(row[j], 0.0f));
    }

    __shared__ float sm[256];
    sm[t] = lmin;
    __syncthreads();
    for (int stride = 128; stride >= 1; stride >>= 1) {
        if (t < stride) sm[t] = fminf(sm[t], sm[t + stride]);
        __syncthreads();
    }

    if (t == 0) {
        float m = sm[0];
        float dp;
        if (m >= FLTMAX) {
            float mx = __uint_as_float(g_maxbits);       // max d2 (clamped >= 0)
            dp = __fdiv_rn(__fsqrt_rn(mx), SQRT_C);
        } else {
            dp = __fdiv_rn(__fsqrt_rn(m), SQRT_C);
        }
        g_score[i] = __fmul_rn(dp, di);
    }
}

// ---------------- kernel 5: exact top-256 (descending, lower-index-first ties) ----
// Bitonic sort of a uint16 index array with indirect comparator on
// key = (score_bits << 32) | (NT-1-idx). Fits in exactly 48KB dynamic smem:
// 8192 floats (32KB) + 8192 uint16 (16KB). No smem opt-in required.
// OUTPUT IS WRITTEN AS float32 (the harness __output__ dtype).
__global__ void k_topk(float* __restrict__ out) {
    extern __shared__ char dyn[];
    float* ss = reinterpret_cast<float*>(dyn);                            // 32KB
    unsigned short* si = reinterpret_cast<unsigned short*>(dyn + NT * 4); // 16KB
    const int t = threadIdx.x;  // 1024 threads

    for (int i = t; i < NT; i += 1024) {
        ss[i] = g_score[i];
        si[i] = (unsigned short)i;
    }
    __syncthreads();

    for (int k = 2; k <= NT; k <<= 1) {
        for (int j = k >> 1; j > 0; j >>= 1) {
            for (int i = t; i < NT; i += 1024) {
                int ixj = i ^ j;
                if (ixj > i) {
                    unsigned short ia = si[i], ib = si[ixj];
                    unsigned long long ka =
                        ((unsigned long long)__float_as_uint(ss[ia]) << 32) |
                        (unsigned int)(NT - 1 - (int)ia);
                    unsigned long long kb =
                        ((unsigned long long)__float_as_uint(ss[ib]) << 32) |
                        (unsigned int)(NT - 1 - (int)ib);
                    bool desc = ((i & k) == 0);
                    if (desc ? (ka < kb) : (ka > kb)) { si[i] = ib; si[ixj] = ia; }
                }
            }
            __syncthreads();
        }
    }

    if (t < NCLUS) out[t] = (float)si[t];   // indices as float32
}

// ---------------- launch ----------------
extern "C" void kernel_launch(void* const* d_in, const int* in_sizes, int n_in,
                              void* d_out, int out_size) {
    const float* X = (const float*)d_in[0];
    float* out = (float*)d_out;

    k_rownorm<<<NT / 8, 256>>>(X);
    k_gemm<<<(64 * 65) / 2, 256>>>(X);
    k_knn<<<NT, 256>>>();
    k_parent<<<NT, 256>>>();
    k_topk<<<1, 1024, 48 * 1024>>>(out);
}